// round 1
// baseline (speedup 1.0000x reference)
#include <cuda_runtime.h>
#include <math.h>

#define BB 2
#define QQ 2048
#define FF 1538

__device__ float g_res[BB * QQ];
__device__ float g_partial[BB];

// ---------------------------------------------------------------------------
// Kernel 1: winding numbers + residuals.
// One warp per query point; lanes stride over faces; warp shuffle reduce.
// ---------------------------------------------------------------------------
__global__ void wn_kernel(const float* __restrict__ points,
                          const float* __restrict__ tris,
                          const float* __restrict__ occ) {
    int gwarp = (blockIdx.x * blockDim.x + threadIdx.x) >> 5;
    int lane  = threadIdx.x & 31;
    if (gwarp >= BB * QQ) return;

    int b = gwarp / QQ;

    float px = points[gwarp * 3 + 0];
    float py = points[gwarp * 3 + 1];
    float pz = points[gwarp * 3 + 2];

    const float* tb = tris + (size_t)b * FF * 9;

    float acc = 0.0f;
    for (int f = lane; f < FF; f += 32) {
        const float* t = tb + f * 9;
        float ax = t[0] - px, ay = t[1] - py, az = t[2] - pz;
        float bx = t[3] - px, by = t[4] - py, bz = t[5] - pz;
        float cx = t[6] - px, cy = t[7] - py, cz = t[8] - pz;

        float na = sqrtf(fmaf(ax, ax, fmaf(ay, ay, az * az)));
        float nb = sqrtf(fmaf(bx, bx, fmaf(by, by, bz * bz)));
        float nc = sqrtf(fmaf(cx, cx, fmaf(cy, cy, cz * cz)));

        float crx = by * cz - bz * cy;
        float cry = bz * cx - bx * cz;
        float crz = bx * cy - by * cx;

        float num = fmaf(ax, crx, fmaf(ay, cry, az * crz));
        float d01 = fmaf(ax, bx, fmaf(ay, by, az * bz));
        float d12 = fmaf(bx, cx, fmaf(by, cy, bz * cz));
        float d02 = fmaf(ax, cx, fmaf(ay, cy, az * cz));

        float den = fmaf(na * nb, nc, fmaf(d01, nc, fmaf(d02, nb, d12 * na)));

        acc += atan2f(num, den);
    }

    #pragma unroll
    for (int o = 16; o > 0; o >>= 1)
        acc += __shfl_xor_sync(0xFFFFFFFFu, acc, o);

    if (lane == 0) {
        // solid angle = 2*atan2; wn = sum / (4*pi) -> acc / (2*pi)
        float wn = acc * 0.15915494309189535f;  // 1/(2*pi)
        g_res[gwarp] = wn - occ[gwarp];
    }
}

// ---------------------------------------------------------------------------
// Kernel 2: per-batch robust weighting (lower-median + MAD) and partial sum.
// One block of 1024 threads per batch row; bitonic sort 2048 floats in smem.
// ---------------------------------------------------------------------------
__device__ __forceinline__ void bitonic_sort_2048(float* s, int tid) {
    for (int k = 2; k <= QQ; k <<= 1) {
        for (int j = k >> 1; j > 0; j >>= 1) {
            #pragma unroll
            for (int base = 0; base < QQ; base += 1024) {
                int idx = base + tid;
                int partner = idx ^ j;
                if (partner > idx) {
                    bool up = ((idx & k) == 0);
                    float a = s[idx];
                    float b = s[partner];
                    if ((a > b) == up) { s[idx] = b; s[partner] = a; }
                }
            }
            __syncthreads();
        }
    }
}

__global__ void robust_kernel() {
    __shared__ float sres[QQ];
    __shared__ float sbuf[QQ];
    int b   = blockIdx.x;
    int tid = threadIdx.x;

    for (int i = tid; i < QQ; i += 1024) {
        float v = g_res[b * QQ + i];
        sres[i] = v;
        sbuf[i] = v;
    }
    __syncthreads();

    bitonic_sort_2048(sbuf, tid);
    float med = sbuf[(QQ - 1) / 2];
    __syncthreads();

    for (int i = tid; i < QQ; i += 1024)
        sbuf[i] = fabsf(sres[i] - med);
    __syncthreads();

    bitonic_sort_2048(sbuf, tid);
    float mad = sbuf[(QQ - 1) / 2];
    __syncthreads();

    float scale = (mad / 0.67449f) * 4.6851f;
    float inv   = 1.0f / scale;

    float sum = 0.0f;
    for (int i = tid; i < QQ; i += 1024) {
        float r  = sres[i];
        float nr = r * inv;
        float t  = 1.0f - nr * nr;
        float w  = (nr >= 1.0f) ? 0.0f : t * t;
        sum += w * r * r;
    }
    __syncthreads();

    sbuf[tid] = sum;
    __syncthreads();
    for (int s = 512; s > 0; s >>= 1) {
        if (tid < s) sbuf[tid] += sbuf[tid + s];
        __syncthreads();
    }
    if (tid == 0) g_partial[b] = sbuf[0];
}

// ---------------------------------------------------------------------------
// Kernel 3: final scalar.
// ---------------------------------------------------------------------------
__global__ void final_kernel(float* __restrict__ out) {
    out[0] = 0.5f * (g_partial[0] + g_partial[1]);
}

extern "C" void kernel_launch(void* const* d_in, const int* in_sizes, int n_in,
                              void* d_out, int out_size) {
    const float* points = (const float*)d_in[0];  // (B,Q,3)
    const float* tris   = (const float*)d_in[1];  // (B,F,3,3)
    const float* occ    = (const float*)d_in[2];  // (B,Q)
    float* out = (float*)d_out;

    // 4096 warps -> 512 blocks x 256 threads
    wn_kernel<<<(BB * QQ * 32) / 256, 256>>>(points, tris, occ);
    robust_kernel<<<BB, 1024>>>();
    final_kernel<<<1, 1>>>(out);
}

// round 2
// speedup vs baseline: 1.6032x; 1.6032x over previous
#include <cuda_runtime.h>
#include <math.h>

#define BB 2
#define QQ 2048
#define FF 1538
#define CH 514          // faces per smem chunk (3 chunks cover 1538)

__device__ float g_res[BB * QQ];
__device__ float g_partial[BB];

// ---------------------------------------------------------------------------
// fast helpers
// ---------------------------------------------------------------------------
__device__ __forceinline__ float sqrt_approx(float x) {
    float r;
    asm("sqrt.approx.f32 %0, %1;" : "=f"(r) : "f"(x));
    return r;
}

// atan2 via quadrant folding + A&S 4.4.49 minimax poly (|err| <= 2e-8 on [0,1])
__device__ __forceinline__ float fast_atan2(float y, float x) {
    float ax = fabsf(x), ay = fabsf(y);
    float mx = fmaxf(ax, ay), mn = fminf(ax, ay);
    float t = __fdividef(mn, mx);
    float s = t * t;
    float p =              0.0028662257f;
    p = fmaf(p, s, -0.0161657367f);
    p = fmaf(p, s,  0.0429096138f);
    p = fmaf(p, s, -0.0752896400f);
    p = fmaf(p, s,  0.1065626393f);
    p = fmaf(p, s, -0.1420889944f);
    p = fmaf(p, s,  0.1999355085f);
    p = fmaf(p, s, -0.3333314528f);
    float r = fmaf(p * s, t, t);             // atan(t), t in [0,1]
    if (ay > ax) r = 1.57079632679f - r;     // atan(|y|/|x|)
    if (x < 0.0f) r = 3.14159265359f - r;
    return copysignf(r, y);
}

// ---------------------------------------------------------------------------
// Kernel 1: winding numbers + residuals.
// One warp per query point (8 warps/block); triangles staged through smem in
// padded 12-float records, read with LDS.128 (conflict-free: stride 12 words).
// ---------------------------------------------------------------------------
__global__ __launch_bounds__(256) void wn_kernel(const float* __restrict__ points,
                                                 const float* __restrict__ tris,
                                                 const float* __restrict__ occ) {
    __shared__ float st[CH * 12];

    int tid  = threadIdx.x;
    int warp = tid >> 5;
    int lane = tid & 31;
    int q    = blockIdx.x * 8 + warp;          // 512 blocks * 8 warps = 4096
    int b    = (blockIdx.x * 8) >> 11;         // batch (uniform per block)

    float px = points[q * 3 + 0];
    float py = points[q * 3 + 1];
    float pz = points[q * 3 + 2];

    const float* tb = tris + (size_t)b * FF * 9;

    float acc = 0.0f;
    for (int base = 0; base < FF; base += CH) {
        int nf = min(CH, FF - base);
        __syncthreads();
        // fill smem: unpack 9-float faces into 12-float padded records
        int total = nf * 9;
        for (int i = tid; i < total; i += 256) {
            int f = i / 9;
            int c = i - f * 9;
            st[f * 12 + c] = tb[base * 9 + i];
        }
        __syncthreads();

        for (int f = lane; f < nf; f += 32) {
            const float4* t4 = (const float4*)&st[f * 12];
            float4 v0 = t4[0];   // ax ay az bx
            float4 v1 = t4[1];   // by bz cx cy
            float4 v2 = t4[2];   // cz . . .

            float ax = v0.x - px, ay = v0.y - py, az = v0.z - pz;
            float bx = v0.w - px, by = v1.x - py, bz = v1.y - pz;
            float cx = v1.z - px, cy = v1.w - py, cz = v2.x - pz;

            float na = sqrt_approx(fmaf(ax, ax, fmaf(ay, ay, az * az)));
            float nb = sqrt_approx(fmaf(bx, bx, fmaf(by, by, bz * bz)));
            float nc = sqrt_approx(fmaf(cx, cx, fmaf(cy, cy, cz * cz)));

            float crx = by * cz - bz * cy;
            float cry = bz * cx - bx * cz;
            float crz = bx * cy - by * cx;

            float num = fmaf(ax, crx, fmaf(ay, cry, az * crz));
            float d01 = fmaf(ax, bx, fmaf(ay, by, az * bz));
            float d12 = fmaf(bx, cx, fmaf(by, cy, bz * cz));
            float d02 = fmaf(ax, cx, fmaf(ay, cy, az * cz));

            float den = fmaf(na * nb, nc, fmaf(d01, nc, fmaf(d02, nb, d12 * na)));

            acc += fast_atan2(num, den);
        }
    }

    #pragma unroll
    for (int o = 16; o > 0; o >>= 1)
        acc += __shfl_xor_sync(0xFFFFFFFFu, acc, o);

    if (lane == 0) {
        float wn = acc * 0.15915494309189535f;  // (2*atan2 sum)/(4*pi)
        g_res[q] = wn - occ[q];
    }
}

// ---------------------------------------------------------------------------
// Kernel 2: robust weighting via 8-bit radix-select medians. 256 threads/batch.
// ---------------------------------------------------------------------------
__device__ __forceinline__ unsigned int fkey(float f) {
    unsigned int u = __float_as_uint(f);
    return (u & 0x80000000u) ? ~u : (u | 0x80000000u);
}
__device__ __forceinline__ float key_to_float(unsigned int k) {
    unsigned int bits = (k & 0x80000000u) ? (k ^ 0x80000000u) : ~k;
    return __uint_as_float(bits);
}

// k-th smallest (k=1023) of QQ keys; 256 threads required.
__device__ unsigned int radix_select_1023(const unsigned int* keys,
                                          unsigned int* hist,
                                          unsigned int* bc, int tid) {
    unsigned int prefix = 0;
    int k = (QQ - 1) / 2;  // 1023
    for (int shift = 24; shift >= 0; shift -= 8) {
        hist[tid] = 0;
        __syncthreads();
        unsigned int hi = (shift == 24) ? 0u : (0xFFFFFFFFu << (shift + 8));
        for (int i = tid; i < QQ; i += 256) {
            unsigned int u = keys[i];
            if ((u & hi) == prefix) atomicAdd(&hist[(u >> shift) & 255u], 1u);
        }
        __syncthreads();
        // inclusive scan over 256 bins (Hillis-Steele)
        for (int off = 1; off < 256; off <<= 1) {
            unsigned int y = (tid >= off) ? hist[tid - off] : 0u;
            __syncthreads();
            hist[tid] += y;
            __syncthreads();
        }
        unsigned int inc = hist[tid];
        unsigned int exc = (tid == 0) ? 0u : hist[tid - 1];
        if ((int)inc > k && (int)exc <= k) {
            bc[0] = (unsigned int)tid;
            bc[1] = (unsigned int)(k - (int)exc);
        }
        __syncthreads();
        prefix |= (bc[0] << shift);
        k = (int)bc[1];
        __syncthreads();
    }
    return prefix;
}

__global__ __launch_bounds__(256) void robust_kernel() {
    __shared__ float        rs[QQ];
    __shared__ unsigned int keys[QQ];
    __shared__ unsigned int hist[256];
    __shared__ unsigned int bc[2];
    __shared__ float        red[8];

    int b   = blockIdx.x;
    int tid = threadIdx.x;

    for (int i = tid; i < QQ; i += 256) {
        float v = g_res[b * QQ + i];
        rs[i]   = v;
        keys[i] = fkey(v);
    }
    __syncthreads();

    float med = key_to_float(radix_select_1023(keys, hist, bc, tid));
    __syncthreads();

    for (int i = tid; i < QQ; i += 256)
        keys[i] = fkey(fabsf(rs[i] - med));
    __syncthreads();

    float mad = key_to_float(radix_select_1023(keys, hist, bc, tid));

    float scale = (mad / 0.67449f) * 4.6851f;

    float sum = 0.0f;
    for (int i = tid; i < QQ; i += 256) {
        float r  = rs[i];
        float nr = r / scale;
        float t  = 1.0f - nr * nr;
        float w  = (nr >= 1.0f) ? 0.0f : t * t;
        sum += w * r * r;
    }

    // block reduce (8 warps)
    #pragma unroll
    for (int o = 16; o > 0; o >>= 1)
        sum += __shfl_xor_sync(0xFFFFFFFFu, sum, o);
    if ((tid & 31) == 0) red[tid >> 5] = sum;
    __syncthreads();
    if (tid == 0) {
        float s = 0.0f;
        #pragma unroll
        for (int w = 0; w < 8; w++) s += red[w];
        g_partial[b] = s;
    }
}

// ---------------------------------------------------------------------------
// Kernel 3: final scalar.
// ---------------------------------------------------------------------------
__global__ void final_kernel(float* __restrict__ out) {
    out[0] = 0.5f * (g_partial[0] + g_partial[1]);
}

extern "C" void kernel_launch(void* const* d_in, const int* in_sizes, int n_in,
                              void* d_out, int out_size) {
    const float* points = (const float*)d_in[0];  // (B,Q,3)
    const float* tris   = (const float*)d_in[1];  // (B,F,3,3)
    const float* occ    = (const float*)d_in[2];  // (B,Q)
    float* out = (float*)d_out;

    wn_kernel<<<(BB * QQ) / 8, 256>>>(points, tris, occ);
    robust_kernel<<<BB, 256>>>();
    final_kernel<<<1, 1>>>(out);
}

// round 3
// speedup vs baseline: 1.6771x; 1.0460x over previous
#include <cuda_runtime.h>
#include <math.h>

#define BB 2
#define QQ 2048
#define FF 1538
#define CH 514          // faces per smem chunk (3 chunks cover 1538)

__device__ float g_res[BB * QQ];
__device__ float g_partial[BB];
__device__ unsigned int g_done = 0;

// ---------------------------------------------------------------------------
// fast helpers
// ---------------------------------------------------------------------------
__device__ __forceinline__ float sqrt_approx(float x) {
    float r;
    asm("sqrt.approx.f32 %0, %1;" : "=f"(r) : "f"(x));
    return r;
}

// atan2 via quadrant folding + minimax poly (|err| <= ~2e-8 on [0,1])
__device__ __forceinline__ float fast_atan2(float y, float x) {
    float ax = fabsf(x), ay = fabsf(y);
    float mx = fmaxf(ax, ay), mn = fminf(ax, ay);
    float t = __fdividef(mn, mx);
    float s = t * t;
    float p =              0.0028662257f;
    p = fmaf(p, s, -0.0161657367f);
    p = fmaf(p, s,  0.0429096138f);
    p = fmaf(p, s, -0.0752896400f);
    p = fmaf(p, s,  0.1065626393f);
    p = fmaf(p, s, -0.1420889944f);
    p = fmaf(p, s,  0.1999355085f);
    p = fmaf(p, s, -0.3333314528f);
    float r = fmaf(p * s, t, t);             // atan(t), t in [0,1]
    if (ay > ax) r = 1.57079632679f - r;     // atan(|y|/|x|)
    if (x < 0.0f) r = 3.14159265359f - r;
    return copysignf(r, y);
}

// ---------------------------------------------------------------------------
// Kernel 1: winding numbers + residuals.
// TWO warps per query point (pair strides faces at 64); 4 queries per 256-thr
// block -> grid 1024 -> ~86% occupancy to hide the atan dependency chain.
// Triangles staged through smem in padded 12-float records (LDS.128,
// conflict-free: stride 12 words).
// ---------------------------------------------------------------------------
__global__ __launch_bounds__(256) void wn_kernel(const float* __restrict__ points,
                                                 const float* __restrict__ tris,
                                                 const float* __restrict__ occ) {
    __shared__ float st[CH * 12];
    __shared__ float sacc[8];

    int tid  = threadIdx.x;
    int warp = tid >> 5;
    int lane = tid & 31;
    int half = warp & 1;                       // which half of the face stride
    int q    = blockIdx.x * 4 + (warp >> 1);   // 1024 blocks * 4 queries = 4096
    int b    = q >> 11;                        // batch

    float px = points[q * 3 + 0];
    float py = points[q * 3 + 1];
    float pz = points[q * 3 + 2];

    const float* tb = tris + (size_t)b * FF * 9;

    float acc = 0.0f;
    for (int base = 0; base < FF; base += CH) {
        int nf = min(CH, FF - base);
        __syncthreads();
        // fill smem: unpack 9-float faces into 12-float padded records
        int total = nf * 9;
        for (int i = tid; i < total; i += 256) {
            int f = i / 9;
            int c = i - f * 9;
            st[f * 12 + c] = tb[base * 9 + i];
        }
        __syncthreads();

        for (int f = half * 32 + lane; f < nf; f += 64) {
            const float4* t4 = (const float4*)&st[f * 12];
            float4 v0 = t4[0];   // ax ay az bx
            float4 v1 = t4[1];   // by bz cx cy
            float4 v2 = t4[2];   // cz . . .

            float ax = v0.x - px, ay = v0.y - py, az = v0.z - pz;
            float bx = v0.w - px, by = v1.x - py, bz = v1.y - pz;
            float cx = v1.z - px, cy = v1.w - py, cz = v2.x - pz;

            float na = sqrt_approx(fmaf(ax, ax, fmaf(ay, ay, az * az)));
            float nb = sqrt_approx(fmaf(bx, bx, fmaf(by, by, bz * bz)));
            float nc = sqrt_approx(fmaf(cx, cx, fmaf(cy, cy, cz * cz)));

            float crx = by * cz - bz * cy;
            float cry = bz * cx - bx * cz;
            float crz = bx * cy - by * cx;

            float num = fmaf(ax, crx, fmaf(ay, cry, az * crz));
            float d01 = fmaf(ax, bx, fmaf(ay, by, az * bz));
            float d12 = fmaf(bx, cx, fmaf(by, cy, bz * cz));
            float d02 = fmaf(ax, cx, fmaf(ay, cy, az * cz));

            float den = fmaf(na * nb, nc, fmaf(d01, nc, fmaf(d02, nb, d12 * na)));

            acc += fast_atan2(num, den);
        }
    }

    #pragma unroll
    for (int o = 16; o > 0; o >>= 1)
        acc += __shfl_xor_sync(0xFFFFFFFFu, acc, o);

    if (lane == 0) sacc[warp] = acc;
    __syncthreads();

    if (half == 0 && lane == 0) {
        float tot = sacc[warp] + sacc[warp + 1];
        float wn  = tot * 0.15915494309189535f;  // (2*atan2 sum)/(4*pi)
        g_res[q] = wn - occ[q];
    }
}

// ---------------------------------------------------------------------------
// Kernel 2: robust weighting via 8-bit radix-select medians (256 thr/batch),
// fused final reduction via last-block threadfence pattern.
// ---------------------------------------------------------------------------
__device__ __forceinline__ unsigned int fkey(float f) {
    unsigned int u = __float_as_uint(f);
    return (u & 0x80000000u) ? ~u : (u | 0x80000000u);
}
__device__ __forceinline__ float key_to_float(unsigned int k) {
    unsigned int bits = (k & 0x80000000u) ? (k ^ 0x80000000u) : ~k;
    return __uint_as_float(bits);
}

// k-th smallest (k=1023) of QQ keys; 256 threads required.
__device__ unsigned int radix_select_1023(const unsigned int* keys,
                                          unsigned int* hist,
                                          unsigned int* bc, int tid) {
    unsigned int prefix = 0;
    int k = (QQ - 1) / 2;  // 1023
    for (int shift = 24; shift >= 0; shift -= 8) {
        hist[tid] = 0;
        __syncthreads();
        unsigned int hi = (shift == 24) ? 0u : (0xFFFFFFFFu << (shift + 8));
        for (int i = tid; i < QQ; i += 256) {
            unsigned int u = keys[i];
            if ((u & hi) == prefix) atomicAdd(&hist[(u >> shift) & 255u], 1u);
        }
        __syncthreads();
        // inclusive scan over 256 bins (Hillis-Steele)
        for (int off = 1; off < 256; off <<= 1) {
            unsigned int y = (tid >= off) ? hist[tid - off] : 0u;
            __syncthreads();
            hist[tid] += y;
            __syncthreads();
        }
        unsigned int inc = hist[tid];
        unsigned int exc = (tid == 0) ? 0u : hist[tid - 1];
        if ((int)inc > k && (int)exc <= k) {
            bc[0] = (unsigned int)tid;
            bc[1] = (unsigned int)(k - (int)exc);
        }
        __syncthreads();
        prefix |= (bc[0] << shift);
        k = (int)bc[1];
        __syncthreads();
    }
    return prefix;
}

__global__ __launch_bounds__(256) void robust_kernel(float* __restrict__ out) {
    __shared__ float        rs[QQ];
    __shared__ unsigned int keys[QQ];
    __shared__ unsigned int hist[256];
    __shared__ unsigned int bc[2];
    __shared__ float        red[8];

    int b   = blockIdx.x;
    int tid = threadIdx.x;

    for (int i = tid; i < QQ; i += 256) {
        float v = g_res[b * QQ + i];
        rs[i]   = v;
        keys[i] = fkey(v);
    }
    __syncthreads();

    float med = key_to_float(radix_select_1023(keys, hist, bc, tid));
    __syncthreads();

    for (int i = tid; i < QQ; i += 256)
        keys[i] = fkey(fabsf(rs[i] - med));
    __syncthreads();

    float mad = key_to_float(radix_select_1023(keys, hist, bc, tid));

    float scale = (mad / 0.67449f) * 4.6851f;

    float sum = 0.0f;
    for (int i = tid; i < QQ; i += 256) {
        float r  = rs[i];
        float nr = r / scale;
        float t  = 1.0f - nr * nr;
        float w  = (nr >= 1.0f) ? 0.0f : t * t;
        sum += w * r * r;
    }

    #pragma unroll
    for (int o = 16; o > 0; o >>= 1)
        sum += __shfl_xor_sync(0xFFFFFFFFu, sum, o);
    if ((tid & 31) == 0) red[tid >> 5] = sum;
    __syncthreads();

    if (tid == 0) {
        float s = 0.0f;
        #pragma unroll
        for (int w = 0; w < 8; w++) s += red[w];
        g_partial[b] = s;
        __threadfence();
        unsigned int prev = atomicAdd(&g_done, 1u);
        if (prev == BB - 1) {
            // last block: both partials visible. 2-float add is order-invariant.
            out[0] = 0.5f * (g_partial[0] + g_partial[1]);
            g_done = 0;  // reset for next graph replay
        }
    }
}

extern "C" void kernel_launch(void* const* d_in, const int* in_sizes, int n_in,
                              void* d_out, int out_size) {
    const float* points = (const float*)d_in[0];  // (B,Q,3)
    const float* tris   = (const float*)d_in[1];  // (B,F,3,3)
    const float* occ    = (const float*)d_in[2];  // (B,Q)
    float* out = (float*)d_out;

    wn_kernel<<<(BB * QQ) / 4, 256>>>(points, tris, occ);
    robust_kernel<<<BB, 256>>>(out);
}

// round 5
// speedup vs baseline: 1.8486x; 1.1023x over previous
#include <cuda_runtime.h>
#include <math.h>

#define BB 2
#define QQ 2048
#define FF 1538
#define CH 514          // faces per smem chunk (3 chunks cover 1538)

__device__ float g_res[BB * QQ];
__device__ float g_partial[BB];
__device__ unsigned int g_done = 0;

// ---------------------------------------------------------------------------
// fast helpers
// ---------------------------------------------------------------------------
__device__ __forceinline__ float sqrt_approx(float x) {
    float r;
    asm("sqrt.approx.f32 %0, %1;" : "=f"(r) : "f"(x));
    return r;
}

// atan2 via quadrant folding + minimax poly (|err| <= ~2e-8 on [0,1])
__device__ __forceinline__ float fast_atan2(float y, float x) {
    float ax = fabsf(x), ay = fabsf(y);
    float mx = fmaxf(ax, ay), mn = fminf(ax, ay);
    float t = __fdividef(mn, mx);
    float s = t * t;
    float p =              0.0028662257f;
    p = fmaf(p, s, -0.0161657367f);
    p = fmaf(p, s,  0.0429096138f);
    p = fmaf(p, s, -0.0752896400f);
    p = fmaf(p, s,  0.1065626393f);
    p = fmaf(p, s, -0.1420889944f);
    p = fmaf(p, s,  0.1999355085f);
    p = fmaf(p, s, -0.3333314528f);
    float r = fmaf(p * s, t, t);             // atan(t), t in [0,1]
    if (ay > ax) r = 1.57079632679f - r;
    if (x < 0.0f) r = 3.14159265359f - r;
    return copysignf(r, y);
}

// ---------------------------------------------------------------------------
// Kernel 1: winding numbers + residuals.
// TWO queries per warp (ILP=2: independent atan/sqrt chains per lane) and
// TWO warps per query pair (face-stride split). 128-thread blocks, 4 queries
// per block -> 1024 blocks. Triangles staged in smem as padded 12-float
// records (LDS.128, conflict-free).
// ---------------------------------------------------------------------------
__global__ __launch_bounds__(128) void wn_kernel(const float* __restrict__ points,
                                                 const float* __restrict__ tris,
                                                 const float* __restrict__ occ) {
    __shared__ float st[CH * 12];
    __shared__ float sacc[8];     // [warp*2 + whichQuery]

    int tid  = threadIdx.x;
    int warp = tid >> 5;          // 0..3
    int lane = tid & 31;
    int pair = warp >> 1;         // query pair 0/1 within block
    int half = warp & 1;          // face-stride half

    int qA = blockIdx.x * 4 + pair * 2;   // 1024 blocks * 4 queries = 4096
    int qB = qA + 1;
    int b  = qA >> 11;                    // batch (uniform per block)

    float pxA = points[qA * 3 + 0], pyA = points[qA * 3 + 1], pzA = points[qA * 3 + 2];
    float pxB = points[qB * 3 + 0], pyB = points[qB * 3 + 1], pzB = points[qB * 3 + 2];

    const float* tb = tris + (size_t)b * FF * 9;

    float accA = 0.0f, accB = 0.0f;
    for (int base = 0; base < FF; base += CH) {
        int nf = min(CH, FF - base);
        __syncthreads();
        int total = nf * 9;
        for (int i = tid; i < total; i += 128) {
            int f = i / 9;
            int c = i - f * 9;
            st[f * 12 + c] = tb[base * 9 + i];
        }
        __syncthreads();

        for (int f = half * 32 + lane; f < nf; f += 64) {
            const float4* t4 = (const float4*)&st[f * 12];
            float4 v0 = t4[0];   // ax ay az bx
            float4 v1 = t4[1];   // by bz cx cy
            float4 v2 = t4[2];   // cz . . .

            // ----- query A -----
            {
                float ax = v0.x - pxA, ay = v0.y - pyA, az = v0.z - pzA;
                float bx = v0.w - pxA, by = v1.x - pyA, bz = v1.y - pzA;
                float cx = v1.z - pxA, cy = v1.w - pyA, cz = v2.x - pzA;

                float na = sqrt_approx(fmaf(ax, ax, fmaf(ay, ay, az * az)));
                float nb = sqrt_approx(fmaf(bx, bx, fmaf(by, by, bz * bz)));
                float nc = sqrt_approx(fmaf(cx, cx, fmaf(cy, cy, cz * cz)));

                float crx = by * cz - bz * cy;
                float cry = bz * cx - bx * cz;
                float crz = bx * cy - by * cx;

                float num = fmaf(ax, crx, fmaf(ay, cry, az * crz));
                float d01 = fmaf(ax, bx, fmaf(ay, by, az * bz));
                float d12 = fmaf(bx, cx, fmaf(by, cy, bz * cz));
                float d02 = fmaf(ax, cx, fmaf(ay, cy, az * cz));

                float den = fmaf(na * nb, nc, fmaf(d01, nc, fmaf(d02, nb, d12 * na)));
                accA += fast_atan2(num, den);
            }
            // ----- query B -----
            {
                float ax = v0.x - pxB, ay = v0.y - pyB, az = v0.z - pzB;
                float bx = v0.w - pxB, by = v1.x - pyB, bz = v1.y - pzB;
                float cx = v1.z - pxB, cy = v1.w - pyB, cz = v2.x - pzB;

                float na = sqrt_approx(fmaf(ax, ax, fmaf(ay, ay, az * az)));
                float nb = sqrt_approx(fmaf(bx, bx, fmaf(by, by, bz * bz)));
                float nc = sqrt_approx(fmaf(cx, cx, fmaf(cy, cy, cz * cz)));

                float crx = by * cz - bz * cy;
                float cry = bz * cx - bx * cz;
                float crz = bx * cy - by * cx;

                float num = fmaf(ax, crx, fmaf(ay, cry, az * crz));
                float d01 = fmaf(ax, bx, fmaf(ay, by, az * bz));
                float d12 = fmaf(bx, cx, fmaf(by, cy, bz * cz));
                float d02 = fmaf(ax, cx, fmaf(ay, cy, az * cz));

                float den = fmaf(na * nb, nc, fmaf(d01, nc, fmaf(d02, nb, d12 * na)));
                accB += fast_atan2(num, den);
            }
        }
    }

    #pragma unroll
    for (int o = 16; o > 0; o >>= 1) {
        accA += __shfl_xor_sync(0xFFFFFFFFu, accA, o);
        accB += __shfl_xor_sync(0xFFFFFFFFu, accB, o);
    }

    if (lane == 0) {
        sacc[warp * 2 + 0] = accA;
        sacc[warp * 2 + 1] = accB;
    }
    __syncthreads();

    if (tid < 4) {  // tid = local query index 0..3
        int p    = tid >> 1;   // pair
        int qloc = tid & 1;    // which query within the pair
        float tot = sacc[(p * 2 + 0) * 2 + qloc] + sacc[(p * 2 + 1) * 2 + qloc];
        int q = blockIdx.x * 4 + tid;
        float wn = tot * 0.15915494309189535f;   // (2*atan2 sum)/(4*pi)
        g_res[q] = wn - occ[q];
    }
}

// ---------------------------------------------------------------------------
// Kernel 2: robust weighting via radix-select medians with warp-shuffle scans
// (5 barriers per shift), fused final reduction (last-block pattern).
// ---------------------------------------------------------------------------
__device__ __forceinline__ unsigned int fkey(float f) {
    unsigned int u = __float_as_uint(f);
    return (u & 0x80000000u) ? ~u : (u | 0x80000000u);
}
__device__ __forceinline__ float key_to_float(unsigned int k) {
    unsigned int bits = (k & 0x80000000u) ? (k ^ 0x80000000u) : ~k;
    return __uint_as_float(bits);
}

// k-th smallest (k=1023) of QQ keys; 256 threads (8 warps) required.
__device__ unsigned int radix_select_1023(const unsigned int* keys,
                                          unsigned int* hist,
                                          unsigned int* wtot,
                                          unsigned int* bc,
                                          int tid) {
    int wid  = tid >> 5;
    int lane = tid & 31;
    unsigned int prefix = 0;
    int k = (QQ - 1) / 2;  // 1023

    for (int shift = 24; shift >= 0; shift -= 8) {
        hist[tid] = 0;
        __syncthreads();                                        // B1
        unsigned int hi = (shift == 24) ? 0u : (0xFFFFFFFFu << (shift + 8));
        #pragma unroll
        for (int i = tid; i < QQ; i += 256) {
            unsigned int u = keys[i];
            if ((u & hi) == prefix) atomicAdd(&hist[(u >> shift) & 255u], 1u);
        }
        __syncthreads();                                        // B2

        unsigned int cnt = hist[tid];
        unsigned int v   = cnt;
        #pragma unroll
        for (int o = 1; o < 32; o <<= 1) {
            unsigned int y = __shfl_up_sync(0xFFFFFFFFu, v, o);
            if (lane >= o) v += y;
        }
        if (lane == 31) wtot[wid] = v;
        __syncthreads();                                        // B3

        if (wid == 0 && lane < 8) {
            unsigned int t0 = wtot[lane];
            unsigned int t  = t0;
            #pragma unroll
            for (int o = 1; o < 8; o <<= 1) {
                unsigned int y = __shfl_up_sync(0x000000FFu, t, o);
                if (lane >= o) t += y;
            }
            wtot[lane] = t - t0;   // exclusive warp offset
        }
        __syncthreads();                                        // B4

        unsigned int inc = v + wtot[wid];
        unsigned int exc = inc - cnt;
        if ((int)exc <= k && k < (int)inc) {
            bc[0] = (unsigned int)tid;
            bc[1] = (unsigned int)(k - (int)exc);
        }
        __syncthreads();                                        // B5
        prefix |= (bc[0] << shift);
        k = (int)bc[1];
        // next-iteration B1 orders bc reads vs. subsequent bc writes
    }
    __syncthreads();
    return prefix;
}

__global__ __launch_bounds__(256) void robust_kernel(float* __restrict__ out) {
    __shared__ float        rs[QQ];
    __shared__ unsigned int keys[QQ];
    __shared__ unsigned int hist[256];
    __shared__ unsigned int wtot[8];
    __shared__ unsigned int bc[2];
    __shared__ float        red[8];

    int b   = blockIdx.x;
    int tid = threadIdx.x;

    for (int i = tid; i < QQ; i += 256) {
        float v = g_res[b * QQ + i];
        rs[i]   = v;
        keys[i] = fkey(v);
    }
    __syncthreads();

    float med = key_to_float(radix_select_1023(keys, hist, wtot, bc, tid));
    __syncthreads();

    for (int i = tid; i < QQ; i += 256)
        keys[i] = fkey(fabsf(rs[i] - med));
    __syncthreads();

    float mad = key_to_float(radix_select_1023(keys, hist, wtot, bc, tid));

    float scale = (mad / 0.67449f) * 4.6851f;

    float sum = 0.0f;
    for (int i = tid; i < QQ; i += 256) {
        float r  = rs[i];
        float nr = r / scale;
        float t  = 1.0f - nr * nr;
        float w  = (nr >= 1.0f) ? 0.0f : t * t;
        sum += w * r * r;
    }

    #pragma unroll
    for (int o = 16; o > 0; o >>= 1)
        sum += __shfl_xor_sync(0xFFFFFFFFu, sum, o);
    if ((tid & 31) == 0) red[tid >> 5] = sum;
    __syncthreads();

    if (tid == 0) {
        float s = 0.0f;
        #pragma unroll
        for (int w = 0; w < 8; w++) s += red[w];
        g_partial[b] = s;
        __threadfence();
        unsigned int prev = atomicAdd(&g_done, 1u);
        if (prev == BB - 1) {
            out[0] = 0.5f * (g_partial[0] + g_partial[1]);
            g_done = 0;  // reset for next graph replay
        }
    }
}

extern "C" void kernel_launch(void* const* d_in, const int* in_sizes, int n_in,
                              void* d_out, int out_size) {
    const float* points = (const float*)d_in[0];  // (B,Q,3)
    const float* tris   = (const float*)d_in[1];  // (B,F,3,3)
    const float* occ    = (const float*)d_in[2];  // (B,Q)
    float* out = (float*)d_out;

    wn_kernel<<<(BB * QQ) / 4, 128>>>(points, tris, occ);
    robust_kernel<<<BB, 256>>>(out);
}

// round 6
// speedup vs baseline: 2.2791x; 1.2329x over previous
#include <cuda_runtime.h>
#include <math.h>

#define BB 2
#define QQ 2048
#define FF 1538
#define CH 514          // faces per smem chunk (3 chunks cover 1538)

__device__ float g_res[BB * QQ];
__device__ float g_partial[BB];
__device__ unsigned int g_done = 0;

// ---------------------------------------------------------------------------
// fast helpers
// ---------------------------------------------------------------------------
__device__ __forceinline__ float sqrt_approx(float x) {
    float r;
    asm("sqrt.approx.f32 %0, %1;" : "=f"(r) : "f"(x));
    return r;
}

// atan2 via quadrant folding + minimax poly (|err| <= ~2e-8 on [0,1])
__device__ __forceinline__ float fast_atan2(float y, float x) {
    float ax = fabsf(x), ay = fabsf(y);
    float mx = fmaxf(ax, ay), mn = fminf(ax, ay);
    float t = __fdividef(mn, mx);
    float s = t * t;
    float p =              0.0028662257f;
    p = fmaf(p, s, -0.0161657367f);
    p = fmaf(p, s,  0.0429096138f);
    p = fmaf(p, s, -0.0752896400f);
    p = fmaf(p, s,  0.1065626393f);
    p = fmaf(p, s, -0.1420889944f);
    p = fmaf(p, s,  0.1999355085f);
    p = fmaf(p, s, -0.3333314528f);
    float r = fmaf(p * s, t, t);             // atan(t), t in [0,1]
    if (ay > ax) r = 1.57079632679f - r;
    if (x < 0.0f) r = 3.14159265359f - r;
    return copysignf(r, y);
}

// ---------------------------------------------------------------------------
// Kernel 1: winding numbers + residuals.
// TWO queries per warp (ILP=2) and TWO warps per query pair (face split).
// 128-thread blocks, 4 queries/block -> 1024 blocks.
// ---------------------------------------------------------------------------
__global__ __launch_bounds__(128) void wn_kernel(const float* __restrict__ points,
                                                 const float* __restrict__ tris,
                                                 const float* __restrict__ occ) {
    __shared__ float st[CH * 12];
    __shared__ float sacc[8];     // [warp*2 + whichQuery]

    int tid  = threadIdx.x;
    int warp = tid >> 5;          // 0..3
    int lane = tid & 31;
    int pair = warp >> 1;         // query pair 0/1 within block
    int half = warp & 1;          // face-stride half

    int qA = blockIdx.x * 4 + pair * 2;   // 1024 blocks * 4 queries = 4096
    int qB = qA + 1;
    int b  = qA >> 11;                    // batch (uniform per block)

    float pxA = points[qA * 3 + 0], pyA = points[qA * 3 + 1], pzA = points[qA * 3 + 2];
    float pxB = points[qB * 3 + 0], pyB = points[qB * 3 + 1], pzB = points[qB * 3 + 2];

    const float* tb = tris + (size_t)b * FF * 9;

    float accA = 0.0f, accB = 0.0f;
    for (int base = 0; base < FF; base += CH) {
        int nf = min(CH, FF - base);
        __syncthreads();
        // stage: one face per thread, strided (no integer division)
        for (int f = tid; f < nf; f += 128) {
            const float* src = tb + (size_t)(base + f) * 9;
            float* dst = &st[f * 12];
            #pragma unroll
            for (int c = 0; c < 9; c++) dst[c] = src[c];
        }
        __syncthreads();

        for (int f = half * 32 + lane; f < nf; f += 64) {
            const float4* t4 = (const float4*)&st[f * 12];
            float4 v0 = t4[0];   // ax ay az bx
            float4 v1 = t4[1];   // by bz cx cy
            float4 v2 = t4[2];   // cz . . .

            // ----- query A -----
            {
                float ax = v0.x - pxA, ay = v0.y - pyA, az = v0.z - pzA;
                float bx = v0.w - pxA, by = v1.x - pyA, bz = v1.y - pzA;
                float cx = v1.z - pxA, cy = v1.w - pyA, cz = v2.x - pzA;

                float na = sqrt_approx(fmaf(ax, ax, fmaf(ay, ay, az * az)));
                float nb = sqrt_approx(fmaf(bx, bx, fmaf(by, by, bz * bz)));
                float nc = sqrt_approx(fmaf(cx, cx, fmaf(cy, cy, cz * cz)));

                float crx = by * cz - bz * cy;
                float cry = bz * cx - bx * cz;
                float crz = bx * cy - by * cx;

                float num = fmaf(ax, crx, fmaf(ay, cry, az * crz));
                float d01 = fmaf(ax, bx, fmaf(ay, by, az * bz));
                float d12 = fmaf(bx, cx, fmaf(by, cy, bz * cz));
                float d02 = fmaf(ax, cx, fmaf(ay, cy, az * cz));

                float den = fmaf(na * nb, nc, fmaf(d01, nc, fmaf(d02, nb, d12 * na)));
                accA += fast_atan2(num, den);
            }
            // ----- query B -----
            {
                float ax = v0.x - pxB, ay = v0.y - pyB, az = v0.z - pzB;
                float bx = v0.w - pxB, by = v1.x - pyB, bz = v1.y - pzB;
                float cx = v1.z - pxB, cy = v1.w - pyB, cz = v2.x - pzB;

                float na = sqrt_approx(fmaf(ax, ax, fmaf(ay, ay, az * az)));
                float nb = sqrt_approx(fmaf(bx, bx, fmaf(by, by, bz * bz)));
                float nc = sqrt_approx(fmaf(cx, cx, fmaf(cy, cy, cz * cz)));

                float crx = by * cz - bz * cy;
                float cry = bz * cx - bx * cz;
                float crz = bx * cy - by * cx;

                float num = fmaf(ax, crx, fmaf(ay, cry, az * crz));
                float d01 = fmaf(ax, bx, fmaf(ay, by, az * bz));
                float d12 = fmaf(bx, cx, fmaf(by, cy, bz * cz));
                float d02 = fmaf(ax, cx, fmaf(ay, cy, az * cz));

                float den = fmaf(na * nb, nc, fmaf(d01, nc, fmaf(d02, nb, d12 * na)));
                accB += fast_atan2(num, den);
            }
        }
    }

    #pragma unroll
    for (int o = 16; o > 0; o >>= 1) {
        accA += __shfl_xor_sync(0xFFFFFFFFu, accA, o);
        accB += __shfl_xor_sync(0xFFFFFFFFu, accB, o);
    }

    if (lane == 0) {
        sacc[warp * 2 + 0] = accA;
        sacc[warp * 2 + 1] = accB;
    }
    __syncthreads();

    if (tid < 4) {  // tid = local query index 0..3
        int p    = tid >> 1;
        int qloc = tid & 1;
        float tot = sacc[(p * 2 + 0) * 2 + qloc] + sacc[(p * 2 + 1) * 2 + qloc];
        int q = blockIdx.x * 4 + tid;
        float wn = tot * 0.15915494309189535f;   // (2*atan2 sum)/(4*pi)
        g_res[q] = wn - occ[q];
    }
}

// ---------------------------------------------------------------------------
// Kernel 2: robust weighting. 1024 threads/batch. Radix-select with
// early-exit small-select once the target bin holds <= 64 keys.
// ---------------------------------------------------------------------------
__device__ __forceinline__ unsigned int fkey(float f) {
    unsigned int u = __float_as_uint(f);
    return (u & 0x80000000u) ? ~u : (u | 0x80000000u);
}
__device__ __forceinline__ float key_to_float(unsigned int k) {
    unsigned int bits = (k & 0x80000000u) ? (k ^ 0x80000000u) : ~k;
    return __uint_as_float(bits);
}

struct SelShared {
    unsigned int hist[256];
    unsigned int wtot[8];
    unsigned int bc[3];      // bin, new k, bin count / result value
    unsigned int cand[64];
    unsigned int ccnt;
};

// k-th smallest (0-indexed) of the QQ keys; 1024 threads required.
__device__ unsigned int radix_select(const unsigned int* keys, SelShared* ss,
                                     int tid, int k) {
    int wid  = tid >> 5;
    int lane = tid & 31;
    unsigned int prefix = 0;

    for (int shift = 24; shift >= 0; shift -= 8) {
        if (tid < 256) ss->hist[tid] = 0;
        if (tid == 0)  ss->ccnt = 0;
        __syncthreads();                                        // B1

        unsigned int hi = (shift == 24) ? 0u : (0xFFFFFFFFu << (shift + 8));
        #pragma unroll
        for (int i = tid; i < QQ; i += 1024) {                  // 2 iterations
            unsigned int u = keys[i];
            if ((u & hi) == prefix) atomicAdd(&ss->hist[(u >> shift) & 255u], 1u);
        }
        __syncthreads();                                        // B2

        if (tid < 256) {
            unsigned int cnt = ss->hist[tid];
            unsigned int v   = cnt;
            #pragma unroll
            for (int o = 1; o < 32; o <<= 1) {
                unsigned int y = __shfl_up_sync(0xFFFFFFFFu, v, o);
                if (lane >= o) v += y;
            }
            if (lane == 31) ss->wtot[wid] = v;
            __syncthreads();                                    // B3 (tid<256)

            if (wid == 0 && lane < 8) {
                unsigned int t0 = ss->wtot[lane];
                unsigned int t  = t0;
                #pragma unroll
                for (int o = 1; o < 8; o <<= 1) {
                    unsigned int y = __shfl_up_sync(0x000000FFu, t, o);
                    if (lane >= o) t += y;
                }
                ss->wtot[lane] = t - t0;   // exclusive warp offset
            }
            __syncthreads();                                    // B4 (tid<256)

            unsigned int inc = v + ss->wtot[wid];
            unsigned int exc = inc - cnt;
            if ((int)exc <= k && k < (int)inc) {
                ss->bc[0] = (unsigned int)tid;
                ss->bc[1] = (unsigned int)(k - (int)exc);
                ss->bc[2] = cnt;
            }
        } else {
            __syncthreads();                                    // B3
            __syncthreads();                                    // B4
        }
        __syncthreads();                                        // B5

        prefix |= (ss->bc[0] << shift);
        k = (int)ss->bc[1];
        unsigned int cnt = ss->bc[2];

        if (shift > 0 && cnt <= 64u) {
            // gather the bin's keys and finish with a rank select
            unsigned int hi2 = 0xFFFFFFFFu << shift;
            #pragma unroll
            for (int i = tid; i < QQ; i += 1024) {
                unsigned int u = keys[i];
                if ((u & hi2) == prefix) {
                    unsigned int p = atomicAdd(&ss->ccnt, 1u);
                    ss->cand[p] = u;
                }
            }
            __syncthreads();
            if (tid < 32) {
                int n = (int)cnt;
                for (int i = tid; i < n; i += 32) {
                    unsigned int v = ss->cand[i];
                    int less = 0, eq = 0;
                    for (int j = 0; j < n; j++) {
                        unsigned int u = ss->cand[j];
                        less += (u < v);
                        eq   += (u == v);
                    }
                    if (less <= k && k < less + eq) ss->bc[2] = v;  // unique value
                }
            }
            __syncthreads();
            return ss->bc[2];
        }
        __syncthreads();   // protect bc/ccnt before next-iteration writes
    }
    return prefix;
}

__global__ __launch_bounds__(1024) void robust_kernel(float* __restrict__ out) {
    __shared__ float        rs[QQ];
    __shared__ unsigned int keys[QQ];
    __shared__ SelShared    ss;
    __shared__ float        red[32];

    int b   = blockIdx.x;
    int tid = threadIdx.x;

    #pragma unroll
    for (int i = tid; i < QQ; i += 1024) {
        float v = g_res[b * QQ + i];
        rs[i]   = v;
        keys[i] = fkey(v);
    }
    __syncthreads();

    float med = key_to_float(radix_select(keys, &ss, tid, (QQ - 1) / 2));
    __syncthreads();

    #pragma unroll
    for (int i = tid; i < QQ; i += 1024)
        keys[i] = fkey(fabsf(rs[i] - med));
    __syncthreads();

    float mad = key_to_float(radix_select(keys, &ss, tid, (QQ - 1) / 2));

    float scale = (mad / 0.67449f) * 4.6851f;

    float sum = 0.0f;
    #pragma unroll
    for (int i = tid; i < QQ; i += 1024) {
        float r  = rs[i];
        float nr = r / scale;
        float t  = 1.0f - nr * nr;
        float w  = (nr >= 1.0f) ? 0.0f : t * t;
        sum += w * r * r;
    }

    #pragma unroll
    for (int o = 16; o > 0; o >>= 1)
        sum += __shfl_xor_sync(0xFFFFFFFFu, sum, o);
    if ((tid & 31) == 0) red[tid >> 5] = sum;
    __syncthreads();

    if (tid < 32) {
        float s = (tid < 32) ? red[tid] : 0.0f;
        #pragma unroll
        for (int o = 16; o > 0; o >>= 1)
            s += __shfl_xor_sync(0xFFFFFFFFu, s, o);
        if (tid == 0) {
            g_partial[b] = s;
            __threadfence();
            unsigned int prev = atomicAdd(&g_done, 1u);
            if (prev == BB - 1) {
                out[0] = 0.5f * (g_partial[0] + g_partial[1]);
                g_done = 0;  // reset for next graph replay
            }
        }
    }
}

extern "C" void kernel_launch(void* const* d_in, const int* in_sizes, int n_in,
                              void* d_out, int out_size) {
    const float* points = (const float*)d_in[0];  // (B,Q,3)
    const float* tris   = (const float*)d_in[1];  // (B,F,3,3)
    const float* occ    = (const float*)d_in[2];  // (B,Q)
    float* out = (float*)d_out;

    wn_kernel<<<(BB * QQ) / 4, 128>>>(points, tris, occ);
    robust_kernel<<<BB, 1024>>>(out);
}